// round 7
// baseline (speedup 1.0000x reference)
#include <cuda_runtime.h>
#include <cuda_bf16.h>
#include <stdint.h>

#define DEV __device__ __forceinline__

static constexpr int Bn  = 8192;
static constexpr int DIN = 1024;
static constexpr int Dd  = 768;
static constexpr int Cc  = 16384;

// ---- scratch: device globals (no allocation allowed) ----
__device__ __align__(1024) __nv_bfloat16 g_Xb[(size_t)Bn * DIN];
__device__ __align__(1024) __nv_bfloat16 g_Wb[(size_t)Dd * DIN];   // W^T
__device__ __align__(1024) __nv_bfloat16 g_E [(size_t)Bn * Dd];    // bf16 embedding
__device__ __align__(1024) int8_t g_Ei[(size_t)Bn * Dd];           // int8 embedding
__device__ __align__(1024) int8_t g_Ci[(size_t)Cc * Dd];           // int8 centroids
__device__ float2 g_eq[Bn];   // {esq, se}  (of quantized row)
__device__ float2 g_cq[Cc];   // {csq, sc}

// ---------------- PTX helpers ----------------
DEV uint32_t smem_u32(const void* p){
    uint32_t a;
    asm("{ .reg .u64 t; cvta.to.shared.u64 t, %1; cvt.u32.u64 %0, t; }" : "=r"(a) : "l"(p));
    return a;
}
DEV uint32_t swz(uint32_t off){ return off ^ ((off >> 3) & 0x70); }   // SW128
DEV void cp16(uint32_t dst, const void* src){
    asm volatile("cp.async.cg.shared.global [%0], [%1], 16;" :: "r"(dst), "l"(src) : "memory");
}
DEV void cp_commit(){ asm volatile("cp.async.commit_group;" ::: "memory"); }
template<int N> DEV void cp_wait(){ asm volatile("cp.async.wait_group %0;" :: "n"(N) : "memory"); }

DEV void ldsm4(uint32_t* r, uint32_t addr){
    asm volatile("ldmatrix.sync.aligned.m8n8.x4.shared.b16 {%0,%1,%2,%3}, [%4];"
                 : "=r"(r[0]), "=r"(r[1]), "=r"(r[2]), "=r"(r[3]) : "r"(addr));
}
DEV void mma_bf16(float* c, const uint32_t* a, uint32_t b0, uint32_t b1){
    asm volatile(
        "mma.sync.aligned.m16n8k16.row.col.f32.bf16.bf16.f32 "
        "{%0,%1,%2,%3}, {%4,%5,%6,%7}, {%8,%9}, {%0,%1,%2,%3};"
        : "+f"(c[0]), "+f"(c[1]), "+f"(c[2]), "+f"(c[3])
        : "r"(a[0]), "r"(a[1]), "r"(a[2]), "r"(a[3]), "r"(b0), "r"(b1));
}
DEV void mma_s8(int* c, const uint32_t* a, uint32_t b0, uint32_t b1){
    asm volatile(
        "mma.sync.aligned.m16n8k32.row.col.s32.s8.s8.s32 "
        "{%0,%1,%2,%3}, {%4,%5,%6,%7}, {%8,%9}, {%0,%1,%2,%3};"
        : "+r"(c[0]), "+r"(c[1]), "+r"(c[2]), "+r"(c[3])
        : "r"(a[0]), "r"(a[1]), "r"(a[2]), "r"(a[3]), "r"(b0), "r"(b1));
}

// ---------------- prep kernels ----------------
__global__ void prep_x(const float4* __restrict__ x){
    size_t i = (size_t)blockIdx.x * blockDim.x + threadIdx.x;
    float4 v = x[i];
    reinterpret_cast<__nv_bfloat162*>(g_Xb)[2*i]   = __floats2bfloat162_rn(v.x, v.y);
    reinterpret_cast<__nv_bfloat162*>(g_Xb)[2*i+1] = __floats2bfloat162_rn(v.z, v.w);
}

__global__ void prep_w(const float* __restrict__ W){
    __shared__ float t[32][33];
    const int bx = blockIdx.x, by = blockIdx.y;
    const int tx = threadIdx.x, ty = threadIdx.y;    // (32,8)
    #pragma unroll
    for (int i = 0; i < 32; i += 8)
        t[ty + i][tx] = W[(size_t)(by*32 + ty + i)*Dd + bx*32 + tx];
    __syncthreads();
    #pragma unroll
    for (int i = 0; i < 32; i += 8)
        g_Wb[(size_t)(bx*32 + ty + i)*DIN + by*32 + tx] = __float2bfloat16(t[tx][ty + i]);
}

// quantize one row (256 threads): buf in smem, two-pass (max, then quantize+sumsq)
template<int SRC>   // 0: centroids fp32, 1: E bf16
__global__ void prep_quant(const float* __restrict__ cent){
    __shared__ float buf[Dd];
    __shared__ float redf[8];
    __shared__ int   redi[8];
    const int row = blockIdx.x, tid = threadIdx.x;

    float mx = 0.f;
    for (int j = tid; j < Dd; j += 256){
        float v = (SRC == 0) ? cent[(size_t)row * Dd + j]
                             : __bfloat162float(g_E[(size_t)row * Dd + j]);
        buf[j] = v;
        mx = fmaxf(mx, fabsf(v));
    }
    #pragma unroll
    for (int o = 16; o; o >>= 1) mx = fmaxf(mx, __shfl_xor_sync(0xffffffffu, mx, o));
    if ((tid & 31) == 0) redf[tid >> 5] = mx;
    __syncthreads();
    mx = fmaxf(fmaxf(fmaxf(redf[0], redf[1]), fmaxf(redf[2], redf[3])),
               fmaxf(fmaxf(redf[4], redf[5]), fmaxf(redf[6], redf[7])));
    const float inv = (mx > 0.f) ? 127.f / mx : 0.f;
    const float s   = mx / 127.f;

    int8_t* dst = (SRC == 0) ? (g_Ci + (size_t)row * Dd) : (g_Ei + (size_t)row * Dd);
    int ssum = 0;
    for (int j = tid; j < Dd; j += 256){
        int q = __float2int_rn(buf[j] * inv);
        q = max(-127, min(127, q));
        dst[j] = (int8_t)q;
        ssum += q * q;
    }
    #pragma unroll
    for (int o = 16; o; o >>= 1) ssum += __shfl_down_sync(0xffffffffu, ssum, o);
    if ((tid & 31) == 0) redi[tid >> 5] = ssum;
    __syncthreads();
    if (tid == 0){
        int tot = redi[0]+redi[1]+redi[2]+redi[3]+redi[4]+redi[5]+redi[6]+redi[7];
        float2 r; r.x = s * s * (float)tot; r.y = s;
        if (SRC == 0) g_cq[row] = r; else g_eq[row] = r;
    }
}

// ------- bf16 GEMM (E producer): CTA 128x256, 8 warps (2x4), BK=64, 4 stages -------
static constexpr int A_ST  = 128 * 128;              // 16 KB
static constexpr int B_ST  = 256 * 128;              // 32 KB
static constexpr int STAGE = A_ST + B_ST;            // 48 KB
static constexpr int NSTG  = 4;
static constexpr int SMEM_BYTES = NSTG * STAGE;      // 192 KB

__global__ void __launch_bounds__(256, 1)
gemm_e(const __nv_bfloat16* __restrict__ A, const __nv_bfloat16* __restrict__ B)
{
    constexpr int NT = DIN / 64;                     // 16 k-chunks
    constexpr int LD = DIN * 2;                      // bytes per row

    extern __shared__ char smem[];
    const uint32_t sb = smem_u32(smem);
    const int tid = threadIdx.x, wid = tid >> 5, lane = tid & 31;
    const int warp_m = wid >> 2, warp_n = wid & 3;
    const int m0 = blockIdx.x * 128, n0 = blockIdx.y * 256;

    const char* gA = reinterpret_cast<const char*>(A) + (size_t)m0 * LD;
    const char* gB = reinterpret_cast<const char*>(B) + (size_t)n0 * LD;

    auto load_stage = [&](int kc){
        const uint32_t base = sb + (kc & (NSTG-1)) * STAGE;
        const size_t koff = (size_t)kc * 128;
        #pragma unroll
        for (int i = 0; i < 4; i++){
            const int t = tid + i * 256, row = t >> 3, c = t & 7;
            cp16(base + swz((uint32_t)(row*128 + c*16)), gA + (size_t)row*LD + koff + c*16);
        }
        #pragma unroll
        for (int i = 0; i < 8; i++){
            const int t = tid + i * 256, row = t >> 3, c = t & 7;
            cp16(base + A_ST + swz((uint32_t)(row*128 + c*16)), gB + (size_t)row*LD + koff + c*16);
        }
        cp_commit();
    };

    float acc[4][8][4];
    #pragma unroll
    for (int i = 0; i < 4; i++)
        #pragma unroll
        for (int j = 0; j < 8; j++)
            #pragma unroll
            for (int r = 0; r < 4; r++) acc[i][j][r] = 0.f;

    load_stage(0); load_stage(1); load_stage(2);
    const int lrow = lane & 15, lcol = (lane >> 4) * 16;

    for (int kc = 0; kc < NT; kc++){
        cp_wait<2>();
        __syncthreads();
        if (kc + 3 < NT) load_stage(kc + 3);
        else             cp_commit();
        const uint32_t base = sb + (kc & (NSTG-1)) * STAGE;
        #pragma unroll
        for (int ks = 0; ks < 4; ks++){
            uint32_t a[4][4], b[4][4];
            const uint32_t cb = (uint32_t)(ks*32 + lcol);
            #pragma unroll
            for (int i = 0; i < 4; i++)
                ldsm4(a[i], base + (swz((uint32_t)((warp_m*64 + i*16 + lrow)*128)) ^ cb));
            #pragma unroll
            for (int j = 0; j < 4; j++)
                ldsm4(b[j], base + A_ST + (swz((uint32_t)((warp_n*64 + j*16 + lrow)*128)) ^ cb));
            #pragma unroll
            for (int i = 0; i < 4; i++)
                #pragma unroll
                for (int j2 = 0; j2 < 8; j2++)
                    mma_bf16(acc[i][j2], a[i], b[j2>>1][j2&1], b[j2>>1][2 + (j2&1)]);
        }
    }

    const int quad = lane >> 2, tq = lane & 3;
    #pragma unroll
    for (int i = 0; i < 4; i++){
        const int mr0 = m0 + warp_m*64 + i*16 + quad;
        #pragma unroll
        for (int j2 = 0; j2 < 8; j2++){
            const int n = n0 + warp_n*64 + j2*8 + tq*2;
            *reinterpret_cast<__nv_bfloat162*>(g_E + (size_t)mr0 * Dd + n) =
                __floats2bfloat162_rn(acc[i][j2][0], acc[i][j2][1]);
            *reinterpret_cast<__nv_bfloat162*>(g_E + (size_t)(mr0+8) * Dd + n) =
                __floats2bfloat162_rn(acc[i][j2][2], acc[i][j2][3]);
        }
    }
}

// ------- int8 GEMM (output): CTA 128x256, BK=128 bytes, K=768 -> 6 chunks -------
__global__ void __launch_bounds__(256, 1)
gemm_s8k(const int8_t* __restrict__ A, const int8_t* __restrict__ B, float* __restrict__ out)
{
    constexpr int NT = Dd / 128;                     // 6 k-chunks (128 int8 each)
    constexpr int LD = Dd;                           // 768 bytes per row

    extern __shared__ char smem[];
    const uint32_t sb = smem_u32(smem);
    const int tid = threadIdx.x, wid = tid >> 5, lane = tid & 31;
    const int warp_m = wid >> 2, warp_n = wid & 3;
    const int m0 = blockIdx.x * 128, n0 = blockIdx.y * 256;

    const char* gA = reinterpret_cast<const char*>(A) + (size_t)m0 * LD;
    const char* gB = reinterpret_cast<const char*>(B) + (size_t)n0 * LD;

    auto load_stage = [&](int kc){
        const uint32_t base = sb + (kc & (NSTG-1)) * STAGE;
        const size_t koff = (size_t)kc * 128;
        #pragma unroll
        for (int i = 0; i < 4; i++){
            const int t = tid + i * 256, row = t >> 3, c = t & 7;
            cp16(base + swz((uint32_t)(row*128 + c*16)), gA + (size_t)row*LD + koff + c*16);
        }
        #pragma unroll
        for (int i = 0; i < 8; i++){
            const int t = tid + i * 256, row = t >> 3, c = t & 7;
            cp16(base + A_ST + swz((uint32_t)(row*128 + c*16)), gB + (size_t)row*LD + koff + c*16);
        }
        cp_commit();
    };

    int acc[4][8][4];
    #pragma unroll
    for (int i = 0; i < 4; i++)
        #pragma unroll
        for (int j = 0; j < 8; j++)
            #pragma unroll
            for (int r = 0; r < 4; r++) acc[i][j][r] = 0;

    load_stage(0); load_stage(1); load_stage(2);
    const int lrow = lane & 15, lcol = (lane >> 4) * 16;

    for (int kc = 0; kc < NT; kc++){
        cp_wait<2>();
        __syncthreads();
        if (kc + 3 < NT) load_stage(kc + 3);
        else             cp_commit();
        const uint32_t base = sb + (kc & (NSTG-1)) * STAGE;
        #pragma unroll
        for (int ks = 0; ks < 4; ks++){              // 4 x k32 per 128B chunk
            uint32_t a[4][4], b[4][4];
            const uint32_t cb = (uint32_t)(ks*32 + lcol);
            #pragma unroll
            for (int i = 0; i < 4; i++)
                ldsm4(a[i], base + (swz((uint32_t)((warp_m*64 + i*16 + lrow)*128)) ^ cb));
            #pragma unroll
            for (int j = 0; j < 4; j++)
                ldsm4(b[j], base + A_ST + (swz((uint32_t)((warp_n*64 + j*16 + lrow)*128)) ^ cb));
            #pragma unroll
            for (int i = 0; i < 4; i++)
                #pragma unroll
                for (int j2 = 0; j2 < 8; j2++)
                    mma_s8(acc[i][j2], a[i], b[j2>>1][j2&1], b[j2>>1][2 + (j2&1)]);
        }
    }

    // epilogue: out = 2*se*sc*dot - esq - csq   (== -||e_q - c_q||^2)
    const int quad = lane >> 2, tq = lane & 3;
    #pragma unroll
    for (int i = 0; i < 4; i++){
        const int mr0 = m0 + warp_m*64 + i*16 + quad;
        const float2 eq0 = __ldg(&g_eq[mr0]);        // {esq, se}
        const float2 eq1 = __ldg(&g_eq[mr0 + 8]);
        #pragma unroll
        for (int j2 = 0; j2 < 8; j2++){
            const int n = n0 + warp_n*64 + j2*8 + tq*2;
            const float4 cq = *reinterpret_cast<const float4*>(
                reinterpret_cast<const char*>(g_cq) + (size_t)n * 8);  // {csq0,sc0,csq1,sc1}
            float2 v0, v1;
            v0.x = 2.f*eq0.y*cq.y*(float)acc[i][j2][0] - eq0.x - cq.x;
            v0.y = 2.f*eq0.y*cq.w*(float)acc[i][j2][1] - eq0.x - cq.z;
            v1.x = 2.f*eq1.y*cq.y*(float)acc[i][j2][2] - eq1.x - cq.x;
            v1.y = 2.f*eq1.y*cq.w*(float)acc[i][j2][3] - eq1.x - cq.z;
            *reinterpret_cast<float2*>(out + (size_t)mr0 * Cc + n)     = v0;
            *reinterpret_cast<float2*>(out + (size_t)(mr0+8) * Cc + n) = v1;
        }
    }
}

extern "C" void kernel_launch(void* const* d_in, const int* in_sizes, int n_in,
                              void* d_out, int out_size)
{
    const float* x = (const float*)d_in[0];
    const float* W = (const float*)d_in[1];
    const float* c = (const float*)d_in[2];
    float* out = (float*)d_out;

    cudaFuncSetAttribute(gemm_e,   cudaFuncAttributeMaxDynamicSharedMemorySize, SMEM_BYTES);
    cudaFuncSetAttribute(gemm_s8k, cudaFuncAttributeMaxDynamicSharedMemorySize, SMEM_BYTES);

    prep_x<<<(Bn * DIN / 4) / 256, 256>>>(reinterpret_cast<const float4*>(x));
    prep_w<<<dim3(Dd / 32, DIN / 32), dim3(32, 8)>>>(W);
    prep_quant<0><<<Cc, 256>>>(c);          // centroids -> int8 + {csq, sc}

    __nv_bfloat16 *xb, *wb;
    int8_t *ei, *ci;
    cudaGetSymbolAddress((void**)&xb, g_Xb);
    cudaGetSymbolAddress((void**)&wb, g_Wb);
    cudaGetSymbolAddress((void**)&ei, g_Ei);
    cudaGetSymbolAddress((void**)&ci, g_Ci);

    gemm_e<<<dim3(Bn / 128, Dd / 256), 256, SMEM_BYTES>>>(xb, wb);
    prep_quant<1><<<Bn, 256>>>(nullptr);    // E -> int8 + {esq, se}
    gemm_s8k<<<dim3(Bn / 128, Cc / 256), 256, SMEM_BYTES>>>(ei, ci, out);
}

// round 8
// speedup vs baseline: 2.4158x; 2.4158x over previous
#include <cuda_runtime.h>
#include <cuda_bf16.h>
#include <cuda_fp16.h>
#include <stdint.h>

#define DEV __device__ __forceinline__

static constexpr int Bn  = 8192;
static constexpr int DIN = 1024;
static constexpr int Dd  = 768;
static constexpr int Cc  = 16384;

// ---- scratch: device globals (no allocation allowed) ----
__device__ __align__(1024) __nv_bfloat16 g_Xb[(size_t)Bn * DIN];
__device__ __align__(1024) __nv_bfloat16 g_Wb[(size_t)Dd * DIN];   // W^T
__device__ __align__(1024) __half g_E [(size_t)Bn * Dd];           // fp16 embedding
__device__ __align__(1024) __half g_Ch[(size_t)Cc * Dd];           // fp16 centroids
__device__ float g_esq[Bn];
__device__ float g_csq[Cc];

// ---------------- PTX helpers ----------------
DEV uint32_t smem_u32(const void* p){
    uint32_t a;
    asm("{ .reg .u64 t; cvta.to.shared.u64 t, %1; cvt.u32.u64 %0, t; }" : "=r"(a) : "l"(p));
    return a;
}
DEV uint32_t swz(uint32_t off){ return off ^ ((off >> 3) & 0x70); }   // SW128
DEV void cp16(uint32_t dst, const void* src){
    asm volatile("cp.async.cg.shared.global [%0], [%1], 16;" :: "r"(dst), "l"(src) : "memory");
}
DEV void cp_commit(){ asm volatile("cp.async.commit_group;" ::: "memory"); }
template<int N> DEV void cp_wait(){ asm volatile("cp.async.wait_group %0;" :: "n"(N) : "memory"); }

DEV void ldsm4(uint32_t* r, uint32_t addr){
    asm volatile("ldmatrix.sync.aligned.m8n8.x4.shared.b16 {%0,%1,%2,%3}, [%4];"
                 : "=r"(r[0]), "=r"(r[1]), "=r"(r[2]), "=r"(r[3]) : "r"(addr));
}
DEV void mma_bf16(float* c, const uint32_t* a, uint32_t b0, uint32_t b1){
    asm volatile(
        "mma.sync.aligned.m16n8k16.row.col.f32.bf16.bf16.f32 "
        "{%0,%1,%2,%3}, {%4,%5,%6,%7}, {%8,%9}, {%0,%1,%2,%3};"
        : "+f"(c[0]), "+f"(c[1]), "+f"(c[2]), "+f"(c[3])
        : "r"(a[0]), "r"(a[1]), "r"(a[2]), "r"(a[3]), "r"(b0), "r"(b1));
}
// f16 inputs, f16 accumulator (2 packed regs)
DEV void mma_f16(uint32_t* c, const uint32_t* a, uint32_t b0, uint32_t b1){
    asm volatile(
        "mma.sync.aligned.m16n8k16.row.col.f16.f16.f16.f16 "
        "{%0,%1}, {%2,%3,%4,%5}, {%6,%7}, {%0,%1};"
        : "+r"(c[0]), "+r"(c[1])
        : "r"(a[0]), "r"(a[1]), "r"(a[2]), "r"(a[3]), "r"(b0), "r"(b1));
}

// ---------------- prep kernels ----------------
__global__ void prep_x(const float4* __restrict__ x){
    size_t i = (size_t)blockIdx.x * blockDim.x + threadIdx.x;
    float4 v = x[i];
    reinterpret_cast<__nv_bfloat162*>(g_Xb)[2*i]   = __floats2bfloat162_rn(v.x, v.y);
    reinterpret_cast<__nv_bfloat162*>(g_Xb)[2*i+1] = __floats2bfloat162_rn(v.z, v.w);
}

__global__ void prep_w(const float* __restrict__ W){
    __shared__ float t[32][33];
    const int bx = blockIdx.x, by = blockIdx.y;
    const int tx = threadIdx.x, ty = threadIdx.y;    // (32,8)
    #pragma unroll
    for (int i = 0; i < 32; i += 8)
        t[ty + i][tx] = W[(size_t)(by*32 + ty + i)*Dd + bx*32 + tx];
    __syncthreads();
    #pragma unroll
    for (int i = 0; i < 32; i += 8)
        g_Wb[(size_t)(bx*32 + ty + i)*DIN + by*32 + tx] = __float2bfloat16(t[tx][ty + i]);
}

__global__ void prep_cent(const float* __restrict__ cent){
    const int row = blockIdx.x, tid = threadIdx.x;
    const float* src = cent + (size_t)row * Dd;
    __half* dst = g_Ch + (size_t)row * Dd;
    float s = 0.f;
    for (int j = tid; j < Dd; j += 256){
        float v = src[j];
        s += v * v;
        dst[j] = __float2half_rn(v);
    }
    __shared__ float red[8];
    #pragma unroll
    for (int o = 16; o; o >>= 1) s += __shfl_down_sync(0xffffffffu, s, o);
    if ((tid & 31) == 0) red[tid >> 5] = s;
    __syncthreads();
    if (tid < 8){
        s = red[tid];
        #pragma unroll
        for (int o = 4; o; o >>= 1) s += __shfl_down_sync(0xffu, s, o);
        if (tid == 0) g_csq[row] = s;
    }
}

__global__ void prep_esq(){
    const int row = blockIdx.x, tid = threadIdx.x;
    const __half* src = g_E + (size_t)row * Dd;
    float s = 0.f;
    for (int j = tid; j < Dd; j += 256){
        float v = __half2float(src[j]);
        s += v * v;
    }
    __shared__ float red[8];
    #pragma unroll
    for (int o = 16; o; o >>= 1) s += __shfl_down_sync(0xffffffffu, s, o);
    if ((tid & 31) == 0) red[tid >> 5] = s;
    __syncthreads();
    if (tid < 8){
        s = red[tid];
        #pragma unroll
        for (int o = 4; o; o >>= 1) s += __shfl_down_sync(0xffu, s, o);
        if (tid == 0) g_esq[row] = s;
    }
}

// shared tiling constants: CTA 128x256, 8 warps (2x4), BK=64, 4 stages
static constexpr int A_ST  = 128 * 128;              // 16 KB
static constexpr int B_ST  = 256 * 128;              // 32 KB
static constexpr int STAGE = A_ST + B_ST;            // 48 KB
static constexpr int NSTG  = 4;
static constexpr int SMEM_BYTES = NSTG * STAGE;      // 192 KB

// ------- bf16 GEMM (E producer): E[8192,768] = Xb @ Wb^T, store fp16 -------
__global__ void __launch_bounds__(256, 1)
gemm_e(const __nv_bfloat16* __restrict__ A, const __nv_bfloat16* __restrict__ B)
{
    constexpr int NT = DIN / 64;
    constexpr int LD = DIN * 2;

    extern __shared__ char smem[];
    const uint32_t sb = smem_u32(smem);
    const int tid = threadIdx.x, wid = tid >> 5, lane = tid & 31;
    const int warp_m = wid >> 2, warp_n = wid & 3;
    const int m0 = blockIdx.x * 128, n0 = blockIdx.y * 256;

    const char* gA = reinterpret_cast<const char*>(A) + (size_t)m0 * LD;
    const char* gB = reinterpret_cast<const char*>(B) + (size_t)n0 * LD;

    auto load_stage = [&](int kc){
        const uint32_t base = sb + (kc & (NSTG-1)) * STAGE;
        const size_t koff = (size_t)kc * 128;
        #pragma unroll
        for (int i = 0; i < 4; i++){
            const int t = tid + i * 256, row = t >> 3, c = t & 7;
            cp16(base + swz((uint32_t)(row*128 + c*16)), gA + (size_t)row*LD + koff + c*16);
        }
        #pragma unroll
        for (int i = 0; i < 8; i++){
            const int t = tid + i * 256, row = t >> 3, c = t & 7;
            cp16(base + A_ST + swz((uint32_t)(row*128 + c*16)), gB + (size_t)row*LD + koff + c*16);
        }
        cp_commit();
    };

    float acc[4][8][4];
    #pragma unroll
    for (int i = 0; i < 4; i++)
        #pragma unroll
        for (int j = 0; j < 8; j++)
            #pragma unroll
            for (int r = 0; r < 4; r++) acc[i][j][r] = 0.f;

    load_stage(0); load_stage(1); load_stage(2);
    const int lrow = lane & 15, lcol = (lane >> 4) * 16;

    for (int kc = 0; kc < NT; kc++){
        cp_wait<2>();
        __syncthreads();
        if (kc + 3 < NT) load_stage(kc + 3);
        else             cp_commit();
        const uint32_t base = sb + (kc & (NSTG-1)) * STAGE;
        #pragma unroll
        for (int ks = 0; ks < 4; ks++){
            uint32_t a[4][4], b[4][4];
            const uint32_t cb = (uint32_t)(ks*32 + lcol);
            #pragma unroll
            for (int i = 0; i < 4; i++)
                ldsm4(a[i], base + swz((uint32_t)((warp_m*64 + i*16 + lrow)*128 + cb)));
            #pragma unroll
            for (int j = 0; j < 4; j++)
                ldsm4(b[j], base + A_ST + swz((uint32_t)((warp_n*64 + j*16 + lrow)*128 + cb)));
            #pragma unroll
            for (int i = 0; i < 4; i++)
                #pragma unroll
                for (int j2 = 0; j2 < 8; j2++)
                    mma_bf16(acc[i][j2], a[i], b[j2>>1][j2&1], b[j2>>1][2 + (j2&1)]);
        }
    }

    const int quad = lane >> 2, tq = lane & 3;
    #pragma unroll
    for (int i = 0; i < 4; i++){
        const int mr0 = m0 + warp_m*64 + i*16 + quad;
        #pragma unroll
        for (int j2 = 0; j2 < 8; j2++){
            const int n = n0 + warp_n*64 + j2*8 + tq*2;
            *reinterpret_cast<__half2*>(g_E + (size_t)mr0 * Dd + n) =
                __floats2half2_rn(acc[i][j2][0], acc[i][j2][1]);
            *reinterpret_cast<__half2*>(g_E + (size_t)(mr0+8) * Dd + n) =
                __floats2half2_rn(acc[i][j2][2], acc[i][j2][3]);
        }
    }
}

// ------- fp16 GEMM (output): out = 2*(E @ Ch^T) - esq - csq, f16 accumulator -------
__global__ void __launch_bounds__(256, 1)
gemm_h(const __half* __restrict__ A, const __half* __restrict__ B, float* __restrict__ out)
{
    constexpr int NT = Dd / 64;                      // 12 k-chunks
    constexpr int LD = Dd * 2;

    extern __shared__ char smem[];
    const uint32_t sb = smem_u32(smem);
    const int tid = threadIdx.x, wid = tid >> 5, lane = tid & 31;
    const int warp_m = wid >> 2, warp_n = wid & 3;
    const int m0 = blockIdx.x * 128, n0 = blockIdx.y * 256;

    const char* gA = reinterpret_cast<const char*>(A) + (size_t)m0 * LD;
    const char* gB = reinterpret_cast<const char*>(B) + (size_t)n0 * LD;

    auto load_stage = [&](int kc){
        const uint32_t base = sb + (kc & (NSTG-1)) * STAGE;
        const size_t koff = (size_t)kc * 128;
        #pragma unroll
        for (int i = 0; i < 4; i++){
            const int t = tid + i * 256, row = t >> 3, c = t & 7;
            cp16(base + swz((uint32_t)(row*128 + c*16)), gA + (size_t)row*LD + koff + c*16);
        }
        #pragma unroll
        for (int i = 0; i < 8; i++){
            const int t = tid + i * 256, row = t >> 3, c = t & 7;
            cp16(base + A_ST + swz((uint32_t)(row*128 + c*16)), gB + (size_t)row*LD + koff + c*16);
        }
        cp_commit();
    };

    // f16x2 accumulators: [m-frag][n-frag][2] — [0]=rows 0-7, [1]=rows 8-15 halves
    uint32_t hacc[4][8][2];
    #pragma unroll
    for (int i = 0; i < 4; i++)
        #pragma unroll
        for (int j = 0; j < 8; j++){ hacc[i][j][0] = 0u; hacc[i][j][1] = 0u; }

    load_stage(0); load_stage(1); load_stage(2);
    const int lrow = lane & 15, lcol = (lane >> 4) * 16;

    for (int kc = 0; kc < NT; kc++){
        cp_wait<2>();
        __syncthreads();
        if (kc + 3 < NT) load_stage(kc + 3);
        else             cp_commit();
        const uint32_t base = sb + (kc & (NSTG-1)) * STAGE;
        #pragma unroll
        for (int ks = 0; ks < 4; ks++){
            uint32_t a[4][4], b[4][4];
            const uint32_t cb = (uint32_t)(ks*32 + lcol);
            #pragma unroll
            for (int i = 0; i < 4; i++)
                ldsm4(a[i], base + swz((uint32_t)((warp_m*64 + i*16 + lrow)*128 + cb)));
            #pragma unroll
            for (int j = 0; j < 4; j++)
                ldsm4(b[j], base + A_ST + swz((uint32_t)((warp_n*64 + j*16 + lrow)*128 + cb)));
            #pragma unroll
            for (int i = 0; i < 4; i++)
                #pragma unroll
                for (int j2 = 0; j2 < 8; j2++)
                    mma_f16(hacc[i][j2], a[i], b[j2>>1][j2&1], b[j2>>1][2 + (j2&1)]);
        }
    }

    // epilogue: out = 2*dot - esq - csq
    const int quad = lane >> 2, tq = lane & 3;
    #pragma unroll
    for (int i = 0; i < 4; i++){
        const int mr0 = m0 + warp_m*64 + i*16 + quad;
        const float e0 = __ldg(&g_esq[mr0]), e1 = __ldg(&g_esq[mr0 + 8]);
        #pragma unroll
        for (int j2 = 0; j2 < 8; j2++){
            const int n = n0 + warp_n*64 + j2*8 + tq*2;
            const float cs0 = __ldg(&g_csq[n]), cs1 = __ldg(&g_csq[n+1]);
            float2 lo = __half22float2(*reinterpret_cast<__half2*>(&hacc[i][j2][0]));
            float2 hi = __half22float2(*reinterpret_cast<__half2*>(&hacc[i][j2][1]));
            float2 v0 = make_float2(2.f*lo.x - e0 - cs0, 2.f*lo.y - e0 - cs1);
            float2 v1 = make_float2(2.f*hi.x - e1 - cs0, 2.f*hi.y - e1 - cs1);
            *reinterpret_cast<float2*>(out + (size_t)mr0 * Cc + n)     = v0;
            *reinterpret_cast<float2*>(out + (size_t)(mr0+8) * Cc + n) = v1;
        }
    }
}

extern "C" void kernel_launch(void* const* d_in, const int* in_sizes, int n_in,
                              void* d_out, int out_size)
{
    const float* x = (const float*)d_in[0];
    const float* W = (const float*)d_in[1];
    const float* c = (const float*)d_in[2];
    float* out = (float*)d_out;

    cudaFuncSetAttribute(gemm_e, cudaFuncAttributeMaxDynamicSharedMemorySize, SMEM_BYTES);
    cudaFuncSetAttribute(gemm_h, cudaFuncAttributeMaxDynamicSharedMemorySize, SMEM_BYTES);

    prep_x<<<(Bn * DIN / 4) / 256, 256>>>(reinterpret_cast<const float4*>(x));
    prep_w<<<dim3(Dd / 32, DIN / 32), dim3(32, 8)>>>(W);
    prep_cent<<<Cc, 256>>>(c);

    __nv_bfloat16 *xb, *wb;
    __half *eh, *ch;
    cudaGetSymbolAddress((void**)&xb, g_Xb);
    cudaGetSymbolAddress((void**)&wb, g_Wb);
    cudaGetSymbolAddress((void**)&eh, g_E);
    cudaGetSymbolAddress((void**)&ch, g_Ch);

    gemm_e<<<dim3(Bn / 128, Dd / 256), 256, SMEM_BYTES>>>(xb, wb);
    prep_esq<<<Bn, 256>>>();
    gemm_h<<<dim3(Bn / 128, Cc / 256), 256, SMEM_BYTES>>>(eh, ch, out);
}

// round 9
// speedup vs baseline: 2.4925x; 1.0317x over previous
#include <cuda_runtime.h>
#include <cuda_bf16.h>
#include <cuda_fp16.h>
#include <stdint.h>

#define DEV __device__ __forceinline__

static constexpr int Bn  = 8192;
static constexpr int DIN = 1024;
static constexpr int Dd  = 768;
static constexpr int Cc  = 16384;

// ---- scratch: device globals (no allocation allowed) ----
__device__ __align__(1024) __nv_bfloat16 g_Xb[(size_t)Bn * DIN];
__device__ __align__(1024) __nv_bfloat16 g_Wb[(size_t)Dd * DIN];   // W^T
__device__ __align__(1024) __half g_E [(size_t)Bn * Dd];           // fp16 embedding
__device__ __align__(1024) __half g_Ch[(size_t)Cc * Dd];           // fp16 centroids
__device__ float g_esqp[(size_t)Bn * 12];   // per-(ntile,warp_n) partials
__device__ float g_esq[Bn];
__device__ float g_csq[Cc];

// ---------------- PTX helpers ----------------
DEV uint32_t smem_u32(const void* p){
    uint32_t a;
    asm("{ .reg .u64 t; cvta.to.shared.u64 t, %1; cvt.u32.u64 %0, t; }" : "=r"(a) : "l"(p));
    return a;
}
DEV uint32_t swz(uint32_t off){ return off ^ ((off >> 3) & 0x70); }   // SW128
DEV void cp16(uint32_t dst, const void* src){
    asm volatile("cp.async.cg.shared.global [%0], [%1], 16;" :: "r"(dst), "l"(src) : "memory");
}
DEV void cp_commit(){ asm volatile("cp.async.commit_group;" ::: "memory"); }
template<int N> DEV void cp_wait(){ asm volatile("cp.async.wait_group %0;" :: "n"(N) : "memory"); }

DEV void ldsm4(uint32_t* r, uint32_t addr){
    asm volatile("ldmatrix.sync.aligned.m8n8.x4.shared.b16 {%0,%1,%2,%3}, [%4];"
                 : "=r"(r[0]), "=r"(r[1]), "=r"(r[2]), "=r"(r[3]) : "r"(addr));
}
DEV void mma_bf16(float* c, const uint32_t* a, uint32_t b0, uint32_t b1){
    asm volatile(
        "mma.sync.aligned.m16n8k16.row.col.f32.bf16.bf16.f32 "
        "{%0,%1,%2,%3}, {%4,%5,%6,%7}, {%8,%9}, {%0,%1,%2,%3};"
        : "+f"(c[0]), "+f"(c[1]), "+f"(c[2]), "+f"(c[3])
        : "r"(a[0]), "r"(a[1]), "r"(a[2]), "r"(a[3]), "r"(b0), "r"(b1));
}
DEV void mma_f16(uint32_t* c, const uint32_t* a, uint32_t b0, uint32_t b1){
    asm volatile(
        "mma.sync.aligned.m16n8k16.row.col.f16.f16.f16.f16 "
        "{%0,%1}, {%2,%3,%4,%5}, {%6,%7}, {%0,%1};"
        : "+r"(c[0]), "+r"(c[1])
        : "r"(a[0]), "r"(a[1]), "r"(a[2]), "r"(a[3]), "r"(b0), "r"(b1));
}

// ---------------- prep kernels ----------------
__global__ void prep_x(const float4* __restrict__ x){
    size_t i = (size_t)blockIdx.x * blockDim.x + threadIdx.x;
    float4 v = x[i];
    reinterpret_cast<__nv_bfloat162*>(g_Xb)[2*i]   = __floats2bfloat162_rn(v.x, v.y);
    reinterpret_cast<__nv_bfloat162*>(g_Xb)[2*i+1] = __floats2bfloat162_rn(v.z, v.w);
}

__global__ void prep_w(const float* __restrict__ W){
    __shared__ float t[32][33];
    const int bx = blockIdx.x, by = blockIdx.y;
    const int tx = threadIdx.x, ty = threadIdx.y;    // (32,8)
    #pragma unroll
    for (int i = 0; i < 32; i += 8)
        t[ty + i][tx] = W[(size_t)(by*32 + ty + i)*Dd + bx*32 + tx];
    __syncthreads();
    #pragma unroll
    for (int i = 0; i < 32; i += 8)
        g_Wb[(size_t)(bx*32 + ty + i)*DIN + by*32 + tx] = __float2bfloat16(t[tx][ty + i]);
}

__global__ void prep_cent(const float* __restrict__ cent){
    const int row = blockIdx.x, tid = threadIdx.x;
    const float* src = cent + (size_t)row * Dd;
    __half* dst = g_Ch + (size_t)row * Dd;
    float s = 0.f;
    for (int j = tid; j < Dd; j += 256){
        float v = src[j];
        s += v * v;
        dst[j] = __float2half_rn(v);
    }
    __shared__ float red[8];
    #pragma unroll
    for (int o = 16; o; o >>= 1) s += __shfl_down_sync(0xffffffffu, s, o);
    if ((tid & 31) == 0) red[tid >> 5] = s;
    __syncthreads();
    if (tid < 8){
        s = red[tid];
        #pragma unroll
        for (int o = 4; o; o >>= 1) s += __shfl_down_sync(0xffu, s, o);
        if (tid == 0) g_csq[row] = s;
    }
}

__global__ void combine_esq(){
    const int row = blockIdx.x * blockDim.x + threadIdx.x;   // 8192 threads
    const float* p = g_esqp + (size_t)row * 12;
    float s = 0.f;
    #pragma unroll
    for (int k = 0; k < 12; k++) s += p[k];
    g_esq[row] = s;
}

// ------- bf16 GEMM (E producer): CTA 128x128, 4 warps (2x2 of 64x64), BK=64,
//         3 stages, 2 CTAs/SM. Stores fp16 E + esq partials. -------
static constexpr int A_ST1  = 128 * 128;             // 16 KB
static constexpr int STAGE1 = 2 * A_ST1;             // 32 KB
static constexpr int NSTG1  = 3;
static constexpr int SMEM1  = NSTG1 * STAGE1;        // 96 KB

__global__ void __launch_bounds__(128, 2)
gemm_e(const __nv_bfloat16* __restrict__ A, const __nv_bfloat16* __restrict__ B)
{
    constexpr int NT = DIN / 64;                     // 16 k-chunks
    constexpr int LD = DIN * 2;

    extern __shared__ char smem[];
    const uint32_t sb = smem_u32(smem);
    const int tid = threadIdx.x, wid = tid >> 5, lane = tid & 31;
    const int warp_m = wid >> 1, warp_n = wid & 1;   // 2 x 2
    const int m0 = blockIdx.x * 128, n0 = blockIdx.y * 128;

    const char* gA = reinterpret_cast<const char*>(A) + (size_t)m0 * LD;
    const char* gB = reinterpret_cast<const char*>(B) + (size_t)n0 * LD;

    auto load_stage = [&](int kc){
        const uint32_t base = sb + (kc % NSTG1) * STAGE1;
        const size_t koff = (size_t)kc * 128;
        #pragma unroll
        for (int i = 0; i < 8; i++){                 // A: 128 rows x 8 chunks
            const int t = tid + i * 128, row = t >> 3, c = t & 7;
            cp16(base + swz((uint32_t)(row*128 + c*16)), gA + (size_t)row*LD + koff + c*16);
        }
        #pragma unroll
        for (int i = 0; i < 8; i++){                 // B: 128 rows x 8 chunks
            const int t = tid + i * 128, row = t >> 3, c = t & 7;
            cp16(base + A_ST1 + swz((uint32_t)(row*128 + c*16)), gB + (size_t)row*LD + koff + c*16);
        }
        cp_commit();
    };

    float acc[4][8][4];
    #pragma unroll
    for (int i = 0; i < 4; i++)
        #pragma unroll
        for (int j = 0; j < 8; j++)
            #pragma unroll
            for (int r = 0; r < 4; r++) acc[i][j][r] = 0.f;

    load_stage(0); load_stage(1);
    const int lrow = lane & 15, lcol = (lane >> 4) * 16;

    for (int kc = 0; kc < NT; kc++){
        cp_wait<1>();
        __syncthreads();
        if (kc + 2 < NT) load_stage(kc + 2);
        else             cp_commit();                 // uniform group counting
        const uint32_t base = sb + (kc % NSTG1) * STAGE1;
        #pragma unroll
        for (int ks = 0; ks < 4; ks++){
            uint32_t a[4][4], b[4][4];
            const uint32_t cb = (uint32_t)(ks*32 + lcol);
            #pragma unroll
            for (int i = 0; i < 4; i++)
                ldsm4(a[i], base + swz((uint32_t)((warp_m*64 + i*16 + lrow)*128 + cb)));
            #pragma unroll
            for (int j = 0; j < 4; j++)
                ldsm4(b[j], base + A_ST1 + swz((uint32_t)((warp_n*64 + j*16 + lrow)*128 + cb)));
            #pragma unroll
            for (int i = 0; i < 4; i++)
                #pragma unroll
                for (int j2 = 0; j2 < 8; j2++)
                    mma_bf16(acc[i][j2], a[i], b[j2>>1][j2&1], b[j2>>1][2 + (j2&1)]);
        }
    }

    // epilogue: store fp16 E, accumulate esq partials from the SAME fp16-rounded values
    const int quad = lane >> 2, tq = lane & 3;
    const int slot = blockIdx.y * 2 + warp_n;        // 6 ntiles x 2 warp_n = 12 slots
    #pragma unroll
    for (int i = 0; i < 4; i++){
        const int mr0 = m0 + warp_m*64 + i*16 + quad;
        float s0 = 0.f, s1 = 0.f;
        #pragma unroll
        for (int j2 = 0; j2 < 8; j2++){
            const int n = n0 + warp_n*64 + j2*8 + tq*2;
            __half2 h0 = __floats2half2_rn(acc[i][j2][0], acc[i][j2][1]);
            __half2 h1 = __floats2half2_rn(acc[i][j2][2], acc[i][j2][3]);
            *reinterpret_cast<__half2*>(g_E + (size_t)mr0 * Dd + n)     = h0;
            *reinterpret_cast<__half2*>(g_E + (size_t)(mr0+8) * Dd + n) = h1;
            float2 f0 = __half22float2(h0), f1 = __half22float2(h1);
            s0 += f0.x*f0.x + f0.y*f0.y;
            s1 += f1.x*f1.x + f1.y*f1.y;
        }
        // reduce across the 4 tq threads (same rows, disjoint columns)
        #pragma unroll
        for (int o = 1; o < 4; o <<= 1){
            s0 += __shfl_xor_sync(0xffffffffu, s0, o);
            s1 += __shfl_xor_sync(0xffffffffu, s1, o);
        }
        if (tq == 0){
            g_esqp[(size_t)mr0     * 12 + slot] = s0;
            g_esqp[(size_t)(mr0+8) * 12 + slot] = s1;
        }
    }
}

// ------- fp16 GEMM (output): CTA 128x256, 8 warps (2x4), BK=64, 4 stages -------
static constexpr int A_ST  = 128 * 128;              // 16 KB
static constexpr int B_ST  = 256 * 128;              // 32 KB
static constexpr int STAGE = A_ST + B_ST;            // 48 KB
static constexpr int NSTG  = 4;
static constexpr int SMEM_BYTES = NSTG * STAGE;      // 192 KB

__global__ void __launch_bounds__(256, 1)
gemm_h(const __half* __restrict__ A, const __half* __restrict__ B, float* __restrict__ out)
{
    constexpr int NT = Dd / 64;                      // 12 k-chunks
    constexpr int LD = Dd * 2;

    extern __shared__ char smem[];
    const uint32_t sb = smem_u32(smem);
    const int tid = threadIdx.x, wid = tid >> 5, lane = tid & 31;
    const int warp_m = wid >> 2, warp_n = wid & 3;
    const int m0 = blockIdx.x * 128, n0 = blockIdx.y * 256;

    const char* gA = reinterpret_cast<const char*>(A) + (size_t)m0 * LD;
    const char* gB = reinterpret_cast<const char*>(B) + (size_t)n0 * LD;

    auto load_stage = [&](int kc){
        const uint32_t base = sb + (kc & (NSTG-1)) * STAGE;
        const size_t koff = (size_t)kc * 128;
        #pragma unroll
        for (int i = 0; i < 4; i++){
            const int t = tid + i * 256, row = t >> 3, c = t & 7;
            cp16(base + swz((uint32_t)(row*128 + c*16)), gA + (size_t)row*LD + koff + c*16);
        }
        #pragma unroll
        for (int i = 0; i < 8; i++){
            const int t = tid + i * 256, row = t >> 3, c = t & 7;
            cp16(base + A_ST + swz((uint32_t)(row*128 + c*16)), gB + (size_t)row*LD + koff + c*16);
        }
        cp_commit();
    };

    uint32_t hacc[4][8][2];
    #pragma unroll
    for (int i = 0; i < 4; i++)
        #pragma unroll
        for (int j = 0; j < 8; j++){ hacc[i][j][0] = 0u; hacc[i][j][1] = 0u; }

    load_stage(0); load_stage(1); load_stage(2);
    const int lrow = lane & 15, lcol = (lane >> 4) * 16;

    for (int kc = 0; kc < NT; kc++){
        cp_wait<2>();
        __syncthreads();
        if (kc + 3 < NT) load_stage(kc + 3);
        else             cp_commit();
        const uint32_t base = sb + (kc & (NSTG-1)) * STAGE;
        #pragma unroll
        for (int ks = 0; ks < 4; ks++){
            uint32_t a[4][4], b[4][4];
            const uint32_t cb = (uint32_t)(ks*32 + lcol);
            #pragma unroll
            for (int i = 0; i < 4; i++)
                ldsm4(a[i], base + swz((uint32_t)((warp_m*64 + i*16 + lrow)*128 + cb)));
            #pragma unroll
            for (int j = 0; j < 4; j++)
                ldsm4(b[j], base + A_ST + swz((uint32_t)((warp_n*64 + j*16 + lrow)*128 + cb)));
            #pragma unroll
            for (int i = 0; i < 4; i++)
                #pragma unroll
                for (int j2 = 0; j2 < 8; j2++)
                    mma_f16(hacc[i][j2], a[i], b[j2>>1][j2&1], b[j2>>1][2 + (j2&1)]);
        }
    }

    const int quad = lane >> 2, tq = lane & 3;
    #pragma unroll
    for (int i = 0; i < 4; i++){
        const int mr0 = m0 + warp_m*64 + i*16 + quad;
        const float e0 = __ldg(&g_esq[mr0]), e1 = __ldg(&g_esq[mr0 + 8]);
        #pragma unroll
        for (int j2 = 0; j2 < 8; j2++){
            const int n = n0 + warp_n*64 + j2*8 + tq*2;
            const float cs0 = __ldg(&g_csq[n]), cs1 = __ldg(&g_csq[n+1]);
            float2 lo = __half22float2(*reinterpret_cast<__half2*>(&hacc[i][j2][0]));
            float2 hi = __half22float2(*reinterpret_cast<__half2*>(&hacc[i][j2][1]));
            float2 v0 = make_float2(2.f*lo.x - e0 - cs0, 2.f*lo.y - e0 - cs1);
            float2 v1 = make_float2(2.f*hi.x - e1 - cs0, 2.f*hi.y - e1 - cs1);
            *reinterpret_cast<float2*>(out + (size_t)mr0 * Cc + n)     = v0;
            *reinterpret_cast<float2*>(out + (size_t)(mr0+8) * Cc + n) = v1;
        }
    }
}

extern "C" void kernel_launch(void* const* d_in, const int* in_sizes, int n_in,
                              void* d_out, int out_size)
{
    const float* x = (const float*)d_in[0];
    const float* W = (const float*)d_in[1];
    const float* c = (const float*)d_in[2];
    float* out = (float*)d_out;

    cudaFuncSetAttribute(gemm_e, cudaFuncAttributeMaxDynamicSharedMemorySize, SMEM1);
    cudaFuncSetAttribute(gemm_h, cudaFuncAttributeMaxDynamicSharedMemorySize, SMEM_BYTES);

    prep_x<<<(Bn * DIN / 4) / 256, 256>>>(reinterpret_cast<const float4*>(x));
    prep_w<<<dim3(Dd / 32, DIN / 32), dim3(32, 8)>>>(W);
    prep_cent<<<Cc, 256>>>(c);

    __nv_bfloat16 *xb, *wb;
    __half *eh, *ch;
    cudaGetSymbolAddress((void**)&xb, g_Xb);
    cudaGetSymbolAddress((void**)&wb, g_Wb);
    cudaGetSymbolAddress((void**)&eh, g_E);
    cudaGetSymbolAddress((void**)&ch, g_Ch);

    gemm_e<<<dim3(Bn / 128, Dd / 128), 128, SMEM1>>>(xb, wb);
    combine_esq<<<Bn / 256, 256>>>();
    gemm_h<<<dim3(Bn / 128, Cc / 256), 256, SMEM_BYTES>>>(eh, ch, out);
}

// round 10
// speedup vs baseline: 2.6955x; 1.0814x over previous
#include <cuda_runtime.h>
#include <cuda_bf16.h>
#include <cuda_fp16.h>
#include <stdint.h>

#define DEV __device__ __forceinline__

static constexpr int Bn  = 8192;
static constexpr int DIN = 1024;
static constexpr int Dd  = 768;
static constexpr int Cc  = 16384;

// ---- scratch: device globals (no allocation allowed) ----
__device__ __align__(1024) __nv_bfloat16 g_Xb[(size_t)Bn * DIN];
__device__ __align__(1024) __nv_bfloat16 g_Wb[(size_t)Dd * DIN];   // W^T
__device__ __align__(1024) __half g_E [(size_t)Bn * Dd];           // fp16 embedding
__device__ __align__(1024) __half g_Ch[(size_t)Cc * Dd];           // fp16 centroids
__device__ float g_esqp[(size_t)Bn * 12];   // per-(ntile,warp_n) partials
__device__ float g_esq[Bn];
__device__ float g_csq[Cc];

// ---------------- PTX helpers ----------------
DEV uint32_t smem_u32(const void* p){
    uint32_t a;
    asm("{ .reg .u64 t; cvta.to.shared.u64 t, %1; cvt.u32.u64 %0, t; }" : "=r"(a) : "l"(p));
    return a;
}
DEV uint32_t swz(uint32_t off){ return off ^ ((off >> 3) & 0x70); }   // SW128
DEV void cp16(uint32_t dst, const void* src){
    asm volatile("cp.async.cg.shared.global [%0], [%1], 16;" :: "r"(dst), "l"(src) : "memory");
}
DEV void cp_commit(){ asm volatile("cp.async.commit_group;" ::: "memory"); }
template<int N> DEV void cp_wait(){ asm volatile("cp.async.wait_group %0;" :: "n"(N) : "memory"); }

DEV void ldsm4(uint32_t* r, uint32_t addr){
    asm volatile("ldmatrix.sync.aligned.m8n8.x4.shared.b16 {%0,%1,%2,%3}, [%4];"
                 : "=r"(r[0]), "=r"(r[1]), "=r"(r[2]), "=r"(r[3]) : "r"(addr));
}
DEV void mma_bf16(float* c, const uint32_t* a, uint32_t b0, uint32_t b1){
    asm volatile(
        "mma.sync.aligned.m16n8k16.row.col.f32.bf16.bf16.f32 "
        "{%0,%1,%2,%3}, {%4,%5,%6,%7}, {%8,%9}, {%0,%1,%2,%3};"
        : "+f"(c[0]), "+f"(c[1]), "+f"(c[2]), "+f"(c[3])
        : "r"(a[0]), "r"(a[1]), "r"(a[2]), "r"(a[3]), "r"(b0), "r"(b1));
}
DEV void mma_f16(uint32_t* c, const uint32_t* a, uint32_t b0, uint32_t b1){
    asm volatile(
        "mma.sync.aligned.m16n8k16.row.col.f16.f16.f16.f16 "
        "{%0,%1}, {%2,%3,%4,%5}, {%6,%7}, {%0,%1};"
        : "+r"(c[0]), "+r"(c[1])
        : "r"(a[0]), "r"(a[1]), "r"(a[2]), "r"(a[3]), "r"(b0), "r"(b1));
}

// ---------------- prep kernels ----------------
__global__ void prep_x(const float4* __restrict__ x){
    size_t i = (size_t)blockIdx.x * blockDim.x + threadIdx.x;
    float4 v = x[i];
    reinterpret_cast<__nv_bfloat162*>(g_Xb)[2*i]   = __floats2bfloat162_rn(v.x, v.y);
    reinterpret_cast<__nv_bfloat162*>(g_Xb)[2*i+1] = __floats2bfloat162_rn(v.z, v.w);
}

__global__ void prep_w(const float* __restrict__ W){
    __shared__ float t[32][33];
    const int bx = blockIdx.x, by = blockIdx.y;
    const int tx = threadIdx.x, ty = threadIdx.y;    // (32,8)
    #pragma unroll
    for (int i = 0; i < 32; i += 8)
        t[ty + i][tx] = W[(size_t)(by*32 + ty + i)*Dd + bx*32 + tx];
    __syncthreads();
    #pragma unroll
    for (int i = 0; i < 32; i += 8)
        g_Wb[(size_t)(bx*32 + ty + i)*DIN + by*32 + tx] = __float2bfloat16(t[tx][ty + i]);
}

__global__ void prep_cent(const float* __restrict__ cent){
    const int row = blockIdx.x, tid = threadIdx.x;
    const float* src = cent + (size_t)row * Dd;
    __half* dst = g_Ch + (size_t)row * Dd;
    float s = 0.f;
    for (int j = tid; j < Dd; j += 256){
        float v = src[j];
        s += v * v;
        dst[j] = __float2half_rn(v);
    }
    __shared__ float red[8];
    #pragma unroll
    for (int o = 16; o; o >>= 1) s += __shfl_down_sync(0xffffffffu, s, o);
    if ((tid & 31) == 0) red[tid >> 5] = s;
    __syncthreads();
    if (tid < 8){
        s = red[tid];
        #pragma unroll
        for (int o = 4; o; o >>= 1) s += __shfl_down_sync(0xffu, s, o);
        if (tid == 0) g_csq[row] = s;
    }
}

__global__ void combine_esq(){
    const int row = blockIdx.x * blockDim.x + threadIdx.x;
    const float* p = g_esqp + (size_t)row * 12;
    float s = 0.f;
    #pragma unroll
    for (int k = 0; k < 12; k++) s += p[k];
    g_esq[row] = s;
}

// shared tile constants: CTA 128x128, 4 warps (2x2 of 64x64), BK=64, 3 stages, 2 CTA/SM
static constexpr int A_ST1  = 128 * 128;             // 16 KB
static constexpr int STAGE1 = 2 * A_ST1;             // 32 KB
static constexpr int NSTG1  = 3;
static constexpr int SMEM1  = NSTG1 * STAGE1;        // 96 KB

// ------- bf16 GEMM (E producer): stores fp16 E + esq partials -------
__global__ void __launch_bounds__(128, 2)
gemm_e(const __nv_bfloat16* __restrict__ A, const __nv_bfloat16* __restrict__ B)
{
    constexpr int NT = DIN / 64;                     // 16 k-chunks
    constexpr int LD = DIN * 2;

    extern __shared__ char smem[];
    const uint32_t sb = smem_u32(smem);
    const int tid = threadIdx.x, wid = tid >> 5, lane = tid & 31;
    const int warp_m = wid >> 1, warp_n = wid & 1;   // 2 x 2
    const int m0 = blockIdx.x * 128, n0 = blockIdx.y * 128;

    const char* gA = reinterpret_cast<const char*>(A) + (size_t)m0 * LD;
    const char* gB = reinterpret_cast<const char*>(B) + (size_t)n0 * LD;

    auto load_stage = [&](int kc){
        const uint32_t base = sb + (kc % NSTG1) * STAGE1;
        const size_t koff = (size_t)kc * 128;
        #pragma unroll
        for (int i = 0; i < 8; i++){                 // A: 128 rows x 8 chunks
            const int t = tid + i * 128, row = t >> 3, c = t & 7;
            cp16(base + swz((uint32_t)(row*128 + c*16)), gA + (size_t)row*LD + koff + c*16);
        }
        #pragma unroll
        for (int i = 0; i < 8; i++){                 // B: 128 rows x 8 chunks
            const int t = tid + i * 128, row = t >> 3, c = t & 7;
            cp16(base + A_ST1 + swz((uint32_t)(row*128 + c*16)), gB + (size_t)row*LD + koff + c*16);
        }
        cp_commit();
    };

    float acc[4][8][4];
    #pragma unroll
    for (int i = 0; i < 4; i++)
        #pragma unroll
        for (int j = 0; j < 8; j++)
            #pragma unroll
            for (int r = 0; r < 4; r++) acc[i][j][r] = 0.f;

    load_stage(0); load_stage(1);
    const int lrow = lane & 15, lcol = (lane >> 4) * 16;

    for (int kc = 0; kc < NT; kc++){
        cp_wait<1>();
        __syncthreads();
        if (kc + 2 < NT) load_stage(kc + 2);
        else             cp_commit();
        const uint32_t base = sb + (kc % NSTG1) * STAGE1;
        #pragma unroll
        for (int ks = 0; ks < 4; ks++){
            uint32_t a[4][4], b[4][4];
            const uint32_t cb = (uint32_t)(ks*32 + lcol);
            #pragma unroll
            for (int i = 0; i < 4; i++)
                ldsm4(a[i], base + swz((uint32_t)((warp_m*64 + i*16 + lrow)*128 + cb)));
            #pragma unroll
            for (int j = 0; j < 4; j++)
                ldsm4(b[j], base + A_ST1 + swz((uint32_t)((warp_n*64 + j*16 + lrow)*128 + cb)));
            #pragma unroll
            for (int i = 0; i < 4; i++)
                #pragma unroll
                for (int j2 = 0; j2 < 8; j2++)
                    mma_bf16(acc[i][j2], a[i], b[j2>>1][j2&1], b[j2>>1][2 + (j2&1)]);
        }
    }

    const int quad = lane >> 2, tq = lane & 3;
    const int slot = blockIdx.y * 2 + warp_n;        // 6 ntiles x 2 warp_n = 12 slots
    #pragma unroll
    for (int i = 0; i < 4; i++){
        const int mr0 = m0 + warp_m*64 + i*16 + quad;
        float s0 = 0.f, s1 = 0.f;
        #pragma unroll
        for (int j2 = 0; j2 < 8; j2++){
            const int n = n0 + warp_n*64 + j2*8 + tq*2;
            __half2 h0 = __floats2half2_rn(acc[i][j2][0], acc[i][j2][1]);
            __half2 h1 = __floats2half2_rn(acc[i][j2][2], acc[i][j2][3]);
            *reinterpret_cast<__half2*>(g_E + (size_t)mr0 * Dd + n)     = h0;
            *reinterpret_cast<__half2*>(g_E + (size_t)(mr0+8) * Dd + n) = h1;
            float2 f0 = __half22float2(h0), f1 = __half22float2(h1);
            s0 += f0.x*f0.x + f0.y*f0.y;
            s1 += f1.x*f1.x + f1.y*f1.y;
        }
        #pragma unroll
        for (int o = 1; o < 4; o <<= 1){
            s0 += __shfl_xor_sync(0xffffffffu, s0, o);
            s1 += __shfl_xor_sync(0xffffffffu, s1, o);
        }
        if (tq == 0){
            g_esqp[(size_t)mr0     * 12 + slot] = s0;
            g_esqp[(size_t)(mr0+8) * 12 + slot] = s1;
        }
    }
}

// ------- fp16 GEMM (output): same 128x128 / 2-CTA-per-SM structure, f16 acc -------
__global__ void __launch_bounds__(128, 2)
gemm_h(const __half* __restrict__ A, const __half* __restrict__ B, float* __restrict__ out)
{
    constexpr int NT = Dd / 64;                      // 12 k-chunks
    constexpr int LD = Dd * 2;

    extern __shared__ char smem[];
    const uint32_t sb = smem_u32(smem);
    const int tid = threadIdx.x, wid = tid >> 5, lane = tid & 31;
    const int warp_m = wid >> 1, warp_n = wid & 1;   // 2 x 2
    const int m0 = blockIdx.x * 128, n0 = blockIdx.y * 128;

    const char* gA = reinterpret_cast<const char*>(A) + (size_t)m0 * LD;
    const char* gB = reinterpret_cast<const char*>(B) + (size_t)n0 * LD;

    auto load_stage = [&](int kc){
        const uint32_t base = sb + (kc % NSTG1) * STAGE1;
        const size_t koff = (size_t)kc * 128;
        #pragma unroll
        for (int i = 0; i < 8; i++){
            const int t = tid + i * 128, row = t >> 3, c = t & 7;
            cp16(base + swz((uint32_t)(row*128 + c*16)), gA + (size_t)row*LD + koff + c*16);
        }
        #pragma unroll
        for (int i = 0; i < 8; i++){
            const int t = tid + i * 128, row = t >> 3, c = t & 7;
            cp16(base + A_ST1 + swz((uint32_t)(row*128 + c*16)), gB + (size_t)row*LD + koff + c*16);
        }
        cp_commit();
    };

    uint32_t hacc[4][8][2];
    #pragma unroll
    for (int i = 0; i < 4; i++)
        #pragma unroll
        for (int j = 0; j < 8; j++){ hacc[i][j][0] = 0u; hacc[i][j][1] = 0u; }

    load_stage(0); load_stage(1);
    const int lrow = lane & 15, lcol = (lane >> 4) * 16;

    for (int kc = 0; kc < NT; kc++){
        cp_wait<1>();
        __syncthreads();
        if (kc + 2 < NT) load_stage(kc + 2);
        else             cp_commit();
        const uint32_t base = sb + (kc % NSTG1) * STAGE1;
        #pragma unroll
        for (int ks = 0; ks < 4; ks++){
            uint32_t a[4][4], b[4][4];
            const uint32_t cb = (uint32_t)(ks*32 + lcol);
            #pragma unroll
            for (int i = 0; i < 4; i++)
                ldsm4(a[i], base + swz((uint32_t)((warp_m*64 + i*16 + lrow)*128 + cb)));
            #pragma unroll
            for (int j = 0; j < 4; j++)
                ldsm4(b[j], base + A_ST1 + swz((uint32_t)((warp_n*64 + j*16 + lrow)*128 + cb)));
            #pragma unroll
            for (int i = 0; i < 4; i++)
                #pragma unroll
                for (int j2 = 0; j2 < 8; j2++)
                    mma_f16(hacc[i][j2], a[i], b[j2>>1][j2&1], b[j2>>1][2 + (j2&1)]);
        }
    }

    const int quad = lane >> 2, tq = lane & 3;
    #pragma unroll
    for (int i = 0; i < 4; i++){
        const int mr0 = m0 + warp_m*64 + i*16 + quad;
        const float e0 = __ldg(&g_esq[mr0]), e1 = __ldg(&g_esq[mr0 + 8]);
        #pragma unroll
        for (int j2 = 0; j2 < 8; j2++){
            const int n = n0 + warp_n*64 + j2*8 + tq*2;
            const float cs0 = __ldg(&g_csq[n]), cs1 = __ldg(&g_csq[n+1]);
            float2 lo = __half22float2(*reinterpret_cast<__half2*>(&hacc[i][j2][0]));
            float2 hi = __half22float2(*reinterpret_cast<__half2*>(&hacc[i][j2][1]));
            float2 v0 = make_float2(2.f*lo.x - e0 - cs0, 2.f*lo.y - e0 - cs1);
            float2 v1 = make_float2(2.f*hi.x - e1 - cs0, 2.f*hi.y - e1 - cs1);
            *reinterpret_cast<float2*>(out + (size_t)mr0 * Cc + n)     = v0;
            *reinterpret_cast<float2*>(out + (size_t)(mr0+8) * Cc + n) = v1;
        }
    }
}

extern "C" void kernel_launch(void* const* d_in, const int* in_sizes, int n_in,
                              void* d_out, int out_size)
{
    const float* x = (const float*)d_in[0];
    const float* W = (const float*)d_in[1];
    const float* c = (const float*)d_in[2];
    float* out = (float*)d_out;

    cudaFuncSetAttribute(gemm_e, cudaFuncAttributeMaxDynamicSharedMemorySize, SMEM1);
    cudaFuncSetAttribute(gemm_h, cudaFuncAttributeMaxDynamicSharedMemorySize, SMEM1);

    prep_x<<<(Bn * DIN / 4) / 256, 256>>>(reinterpret_cast<const float4*>(x));
    prep_w<<<dim3(Dd / 32, DIN / 32), dim3(32, 8)>>>(W);
    prep_cent<<<Cc, 256>>>(c);

    __nv_bfloat16 *xb, *wb;
    __half *eh, *ch;
    cudaGetSymbolAddress((void**)&xb, g_Xb);
    cudaGetSymbolAddress((void**)&wb, g_Wb);
    cudaGetSymbolAddress((void**)&eh, g_E);
    cudaGetSymbolAddress((void**)&ch, g_Ch);

    gemm_e<<<dim3(Bn / 128, Dd / 128), 128, SMEM1>>>(xb, wb);
    combine_esq<<<Bn / 256, 256>>>();
    gemm_h<<<dim3(Bn / 128, Cc / 128), 128, SMEM1>>>(eh, ch, out);
}

// round 11
// speedup vs baseline: 2.8799x; 1.0684x over previous
#include <cuda_runtime.h>
#include <cuda_bf16.h>
#include <cuda_fp16.h>
#include <stdint.h>

#define DEV __device__ __forceinline__

static constexpr int Bn  = 8192;
static constexpr int DIN = 1024;
static constexpr int Dd  = 768;
static constexpr int Cc  = 16384;

// ---- scratch: device globals (no allocation allowed) ----
__device__ __align__(1024) __nv_bfloat16 g_Xb[(size_t)Bn * DIN];
__device__ __align__(1024) __nv_bfloat16 g_Wb[(size_t)Dd * DIN];   // W^T
__device__ __align__(1024) __half g_E [(size_t)Bn * Dd];           // fp16 embedding
__device__ __align__(1024) __half g_Ch[(size_t)Cc * Dd];           // fp16 centroids
__device__ float g_esqp[(size_t)Bn * 12];   // per-(ntile,warp_n) partials
__device__ float g_esq[Bn];
__device__ float g_csq[Cc];

// ---------------- PTX helpers ----------------
DEV uint32_t smem_u32(const void* p){
    uint32_t a;
    asm("{ .reg .u64 t; cvta.to.shared.u64 t, %1; cvt.u32.u64 %0, t; }" : "=r"(a) : "l"(p));
    return a;
}
DEV uint32_t swz(uint32_t off){ return off ^ ((off >> 3) & 0x70); }   // SW128
DEV void cp16(uint32_t dst, const void* src){
    asm volatile("cp.async.cg.shared.global [%0], [%1], 16;" :: "r"(dst), "l"(src) : "memory");
}
DEV void cp_commit(){ asm volatile("cp.async.commit_group;" ::: "memory"); }
template<int N> DEV void cp_wait(){ asm volatile("cp.async.wait_group %0;" :: "n"(N) : "memory"); }

DEV void ldsm4(uint32_t* r, uint32_t addr){
    asm volatile("ldmatrix.sync.aligned.m8n8.x4.shared.b16 {%0,%1,%2,%3}, [%4];"
                 : "=r"(r[0]), "=r"(r[1]), "=r"(r[2]), "=r"(r[3]) : "r"(addr));
}
DEV void mma_f16(uint32_t* c, const uint32_t* a, uint32_t b0, uint32_t b1){
    asm volatile(
        "mma.sync.aligned.m16n8k16.row.col.f16.f16.f16.f16 "
        "{%0,%1}, {%2,%3,%4,%5}, {%6,%7}, {%0,%1};"
        : "+r"(c[0]), "+r"(c[1])
        : "r"(a[0]), "r"(a[1]), "r"(a[2]), "r"(a[3]), "r"(b0), "r"(b1));
}
// bf16 inputs with f16 accumulator are not a legal combo; gemm_e now uses fp16 inputs.

// ---------------- prep kernels ----------------
__global__ void prep_x(const float4* __restrict__ x){
    size_t i = (size_t)blockIdx.x * blockDim.x + threadIdx.x;
    float4 v = x[i];
    // store x as fp16 (better mantissa than bf16; |x| ~ N(0,1), well within range)
    reinterpret_cast<__half2*>(g_Xb)[2*i]   = __floats2half2_rn(v.x, v.y);
    reinterpret_cast<__half2*>(g_Xb)[2*i+1] = __floats2half2_rn(v.z, v.w);
}

__global__ void prep_w(const float* __restrict__ W){
    __shared__ float t[32][33];
    const int bx = blockIdx.x, by = blockIdx.y;
    const int tx = threadIdx.x, ty = threadIdx.y;    // (32,8)
    #pragma unroll
    for (int i = 0; i < 32; i += 8)
        t[ty + i][tx] = W[(size_t)(by*32 + ty + i)*Dd + bx*32 + tx];
    __syncthreads();
    #pragma unroll
    for (int i = 0; i < 32; i += 8)
        reinterpret_cast<__half*>(g_Wb)[(size_t)(bx*32 + ty + i)*DIN + by*32 + tx] =
            __float2half_rn(t[tx][ty + i]);
}

__global__ void prep_cent(const float* __restrict__ cent){
    const int row = blockIdx.x, tid = threadIdx.x;   // 256 threads
    const float4* src4 = reinterpret_cast<const float4*>(cent + (size_t)row * Dd);
    __half2* dst2 = reinterpret_cast<__half2*>(g_Ch + (size_t)row * Dd);
    float s = 0.f;
    if (tid < 192){                                  // 192 float4 per row
        float4 v = src4[tid];
        s = v.x*v.x + v.y*v.y + v.z*v.z + v.w*v.w;
        dst2[tid*2]   = __floats2half2_rn(v.x, v.y);
        dst2[tid*2+1] = __floats2half2_rn(v.z, v.w);
    }
    __shared__ float red[8];
    #pragma unroll
    for (int o = 16; o; o >>= 1) s += __shfl_down_sync(0xffffffffu, s, o);
    if ((tid & 31) == 0) red[tid >> 5] = s;
    __syncthreads();
    if (tid < 8){
        s = red[tid];
        #pragma unroll
        for (int o = 4; o; o >>= 1) s += __shfl_down_sync(0xffu, s, o);
        if (tid == 0) g_csq[row] = s;
    }
}

__global__ void combine_esq(){
    const int row = blockIdx.x * blockDim.x + threadIdx.x;
    const float* p = g_esqp + (size_t)row * 12;
    float s = 0.f;
    #pragma unroll
    for (int k = 0; k < 12; k++) s += p[k];
    g_esq[row] = s;
}

// tile constants: CTA 128x128, 4 warps (2x2 of 64x64), BK=64, 2 stages, 3 CTA/SM
static constexpr int A_ST1  = 128 * 128;             // 16 KB
static constexpr int STAGE1 = 2 * A_ST1;             // 32 KB
static constexpr int NSTG1  = 2;
static constexpr int SMEM1  = NSTG1 * STAGE1;        // 64 KB

// ------- fp16 GEMM (E producer): E = Xh @ Wh^T, f16 acc, stores fp16 E + esq partials -------
__global__ void __launch_bounds__(128, 3)
gemm_e(const __half* __restrict__ A, const __half* __restrict__ B)
{
    constexpr int NT = DIN / 64;                     // 16 k-chunks
    constexpr int LD = DIN * 2;

    extern __shared__ char smem[];
    const uint32_t sb = smem_u32(smem);
    const int tid = threadIdx.x, wid = tid >> 5, lane = tid & 31;
    const int warp_m = wid >> 1, warp_n = wid & 1;   // 2 x 2
    const int m0 = blockIdx.x * 128, n0 = blockIdx.y * 128;

    const char* gA = reinterpret_cast<const char*>(A) + (size_t)m0 * LD;
    const char* gB = reinterpret_cast<const char*>(B) + (size_t)n0 * LD;

    auto load_stage = [&](int kc){
        const uint32_t base = sb + (kc & 1) * STAGE1;
        const size_t koff = (size_t)kc * 128;
        #pragma unroll
        for (int i = 0; i < 8; i++){                 // A: 128 rows x 8 chunks
            const int t = tid + i * 128, row = t >> 3, c = t & 7;
            cp16(base + swz((uint32_t)(row*128 + c*16)), gA + (size_t)row*LD + koff + c*16);
        }
        #pragma unroll
        for (int i = 0; i < 8; i++){                 // B: 128 rows x 8 chunks
            const int t = tid + i * 128, row = t >> 3, c = t & 7;
            cp16(base + A_ST1 + swz((uint32_t)(row*128 + c*16)), gB + (size_t)row*LD + koff + c*16);
        }
        cp_commit();
    };

    uint32_t hacc[4][8][2];
    #pragma unroll
    for (int i = 0; i < 4; i++)
        #pragma unroll
        for (int j = 0; j < 8; j++){ hacc[i][j][0] = 0u; hacc[i][j][1] = 0u; }

    load_stage(0); load_stage(1);
    const int lrow = lane & 15, lcol = (lane >> 4) * 16;

    for (int kc = 0; kc < NT; kc++){
        cp_wait<1>();
        __syncthreads();
        const uint32_t base = sb + (kc & 1) * STAGE1;
        #pragma unroll
        for (int ks = 0; ks < 4; ks++){
            uint32_t a[4][4], b[4][4];
            const uint32_t cb = (uint32_t)(ks*32 + lcol);
            #pragma unroll
            for (int i = 0; i < 4; i++)
                ldsm4(a[i], base + swz((uint32_t)((warp_m*64 + i*16 + lrow)*128 + cb)));
            #pragma unroll
            for (int j = 0; j < 4; j++)
                ldsm4(b[j], base + A_ST1 + swz((uint32_t)((warp_n*64 + j*16 + lrow)*128 + cb)));
            #pragma unroll
            for (int i = 0; i < 4; i++)
                #pragma unroll
                for (int j2 = 0; j2 < 8; j2++)
                    mma_f16(hacc[i][j2], a[i], b[j2>>1][j2&1], b[j2>>1][2 + (j2&1)]);
        }
        __syncthreads();                              // all reads done before overwrite
        if (kc + 2 < NT) load_stage(kc + 2);
        else             cp_commit();                 // uniform group counting
    }

    // epilogue: store fp16 E, esq partials from the SAME fp16 values
    const int quad = lane >> 2, tq = lane & 3;
    const int slot = blockIdx.y * 2 + warp_n;        // 6 ntiles x 2 warp_n = 12 slots
    #pragma unroll
    for (int i = 0; i < 4; i++){
        const int mr0 = m0 + warp_m*64 + i*16 + quad;
        float s0 = 0.f, s1 = 0.f;
        #pragma unroll
        for (int j2 = 0; j2 < 8; j2++){
            const int n = n0 + warp_n*64 + j2*8 + tq*2;
            __half2 h0 = *reinterpret_cast<__half2*>(&hacc[i][j2][0]);
            __half2 h1 = *reinterpret_cast<__half2*>(&hacc[i][j2][1]);
            *reinterpret_cast<__half2*>(g_E + (size_t)mr0 * Dd + n)     = h0;
            *reinterpret_cast<__half2*>(g_E + (size_t)(mr0+8) * Dd + n) = h1;
            float2 f0 = __half22float2(h0), f1 = __half22float2(h1);
            s0 += f0.x*f0.x + f0.y*f0.y;
            s1 += f1.x*f1.x + f1.y*f1.y;
        }
        #pragma unroll
        for (int o = 1; o < 4; o <<= 1){
            s0 += __shfl_xor_sync(0xffffffffu, s0, o);
            s1 += __shfl_xor_sync(0xffffffffu, s1, o);
        }
        if (tq == 0){
            g_esqp[(size_t)mr0     * 12 + slot] = s0;
            g_esqp[(size_t)(mr0+8) * 12 + slot] = s1;
        }
    }
}

// ------- fp16 GEMM (output): out = 2*(E @ Ch^T) - esq - csq, f16 acc -------
__global__ void __launch_bounds__(128, 3)
gemm_h(const __half* __restrict__ A, const __half* __restrict__ B, float* __restrict__ out)
{
    constexpr int NT = Dd / 64;                      // 12 k-chunks
    constexpr int LD = Dd * 2;

    extern __shared__ char smem[];
    const uint32_t sb = smem_u32(smem);
    const int tid = threadIdx.x, wid = tid >> 5, lane = tid & 31;
    const int warp_m = wid >> 1, warp_n = wid & 1;   // 2 x 2
    const int m0 = blockIdx.x * 128, n0 = blockIdx.y * 128;

    const char* gA = reinterpret_cast<const char*>(A) + (size_t)m0 * LD;
    const char* gB = reinterpret_cast<const char*>(B) + (size_t)n0 * LD;

    auto load_stage = [&](int kc){
        const uint32_t base = sb + (kc & 1) * STAGE1;
        const size_t koff = (size_t)kc * 128;
        #pragma unroll
        for (int i = 0; i < 8; i++){
            const int t = tid + i * 128, row = t >> 3, c = t & 7;
            cp16(base + swz((uint32_t)(row*128 + c*16)), gA + (size_t)row*LD + koff + c*16);
        }
        #pragma unroll
        for (int i = 0; i < 8; i++){
            const int t = tid + i * 128, row = t >> 3, c = t & 7;
            cp16(base + A_ST1 + swz((uint32_t)(row*128 + c*16)), gB + (size_t)row*LD + koff + c*16);
        }
        cp_commit();
    };

    uint32_t hacc[4][8][2];
    #pragma unroll
    for (int i = 0; i < 4; i++)
        #pragma unroll
        for (int j = 0; j < 8; j++){ hacc[i][j][0] = 0u; hacc[i][j][1] = 0u; }

    load_stage(0); load_stage(1);
    const int lrow = lane & 15, lcol = (lane >> 4) * 16;

    for (int kc = 0; kc < NT; kc++){
        cp_wait<1>();
        __syncthreads();
        const uint32_t base = sb + (kc & 1) * STAGE1;
        #pragma unroll
        for (int ks = 0; ks < 4; ks++){
            uint32_t a[4][4], b[4][4];
            const uint32_t cb = (uint32_t)(ks*32 + lcol);
            #pragma unroll
            for (int i = 0; i < 4; i++)
                ldsm4(a[i], base + swz((uint32_t)((warp_m*64 + i*16 + lrow)*128 + cb)));
            #pragma unroll
            for (int j = 0; j < 4; j++)
                ldsm4(b[j], base + A_ST1 + swz((uint32_t)((warp_n*64 + j*16 + lrow)*128 + cb)));
            #pragma unroll
            for (int i = 0; i < 4; i++)
                #pragma unroll
                for (int j2 = 0; j2 < 8; j2++)
                    mma_f16(hacc[i][j2], a[i], b[j2>>1][j2&1], b[j2>>1][2 + (j2&1)]);
        }
        __syncthreads();
        if (kc + 2 < NT) load_stage(kc + 2);
        else             cp_commit();
    }

    const int quad = lane >> 2, tq = lane & 3;
    #pragma unroll
    for (int i = 0; i < 4; i++){
        const int mr0 = m0 + warp_m*64 + i*16 + quad;
        const float e0 = __ldg(&g_esq[mr0]), e1 = __ldg(&g_esq[mr0 + 8]);
        #pragma unroll
        for (int j2 = 0; j2 < 8; j2++){
            const int n = n0 + warp_n*64 + j2*8 + tq*2;
            const float cs0 = __ldg(&g_csq[n]), cs1 = __ldg(&g_csq[n+1]);
            float2 lo = __half22float2(*reinterpret_cast<__half2*>(&hacc[i][j2][0]));
            float2 hi = __half22float2(*reinterpret_cast<__half2*>(&hacc[i][j2][1]));
            float2 v0 = make_float2(2.f*lo.x - e0 - cs0, 2.f*lo.y - e0 - cs1);
            float2 v1 = make_float2(2.f*hi.x - e1 - cs0, 2.f*hi.y - e1 - cs1);
            *reinterpret_cast<float2*>(out + (size_t)mr0 * Cc + n)     = v0;
            *reinterpret_cast<float2*>(out + (size_t)(mr0+8) * Cc + n) = v1;
        }
    }
}

extern "C" void kernel_launch(void* const* d_in, const int* in_sizes, int n_in,
                              void* d_out, int out_size)
{
    const float* x = (const float*)d_in[0];
    const float* W = (const float*)d_in[1];
    const float* c = (const float*)d_in[2];
    float* out = (float*)d_out;

    cudaFuncSetAttribute(gemm_e, cudaFuncAttributeMaxDynamicSharedMemorySize, SMEM1);
    cudaFuncSetAttribute(gemm_h, cudaFuncAttributeMaxDynamicSharedMemorySize, SMEM1);

    prep_x<<<(Bn * DIN / 4) / 256, 256>>>(reinterpret_cast<const float4*>(x));
    prep_w<<<dim3(Dd / 32, DIN / 32), dim3(32, 8)>>>(W);
    prep_cent<<<Cc, 256>>>(c);

    __half *xh, *wh, *eh, *ch;
    cudaGetSymbolAddress((void**)&xh, g_Xb);
    cudaGetSymbolAddress((void**)&wh, g_Wb);
    cudaGetSymbolAddress((void**)&eh, g_E);
    cudaGetSymbolAddress((void**)&ch, g_Ch);

    gemm_e<<<dim3(Bn / 128, Dd / 128), 128, SMEM1>>>(xh, wh);
    combine_esq<<<Bn / 256, 256>>>();
    gemm_h<<<dim3(Bn / 128, Cc / 128), 128, SMEM1>>>(eh, ch, out);
}

// round 12
// speedup vs baseline: 3.0220x; 1.0493x over previous
#include <cuda_runtime.h>
#include <cuda_bf16.h>
#include <cuda_fp16.h>
#include <stdint.h>

#define DEV __device__ __forceinline__

static constexpr int Bn  = 8192;
static constexpr int DIN = 1024;
static constexpr int Dd  = 768;
static constexpr int Cc  = 16384;

// ---- scratch: device globals (no allocation allowed) ----
__device__ __align__(1024) __half g_Xh[(size_t)Bn * DIN];
__device__ __align__(1024) __half g_Wh[(size_t)Dd * DIN];          // W^T
__device__ __align__(1024) __half g_E [(size_t)Bn * Dd];           // fp16 embedding
__device__ __align__(1024) __half g_Ch[(size_t)Cc * Dd];           // fp16 centroids
__device__ float g_esqp[(size_t)Bn * 12];   // per-(ntile,warp_n) partials
__device__ float g_esq[Bn];
__device__ float g_csq[Cc];

// ---------------- PTX helpers ----------------
DEV uint32_t smem_u32(const void* p){
    uint32_t a;
    asm("{ .reg .u64 t; cvta.to.shared.u64 t, %1; cvt.u32.u64 %0, t; }" : "=r"(a) : "l"(p));
    return a;
}
DEV uint32_t swz(uint32_t off){ return off ^ ((off >> 3) & 0x70); }   // SW128
DEV void cp16(uint32_t dst, const void* src){
    asm volatile("cp.async.cg.shared.global [%0], [%1], 16;" :: "r"(dst), "l"(src) : "memory");
}
DEV void cp_commit(){ asm volatile("cp.async.commit_group;" ::: "memory"); }
template<int N> DEV void cp_wait(){ asm volatile("cp.async.wait_group %0;" :: "n"(N) : "memory"); }

DEV void ldsm4(uint32_t* r, uint32_t addr){
    asm volatile("ldmatrix.sync.aligned.m8n8.x4.shared.b16 {%0,%1,%2,%3}, [%4];"
                 : "=r"(r[0]), "=r"(r[1]), "=r"(r[2]), "=r"(r[3]) : "r"(addr));
}
DEV void mma_f16(uint32_t* c, const uint32_t* a, uint32_t b0, uint32_t b1){
    asm volatile(
        "mma.sync.aligned.m16n8k16.row.col.f16.f16.f16.f16 "
        "{%0,%1}, {%2,%3,%4,%5}, {%6,%7}, {%0,%1};"
        : "+r"(c[0]), "+r"(c[1])
        : "r"(a[0]), "r"(a[1]), "r"(a[2]), "r"(a[3]), "r"(b0), "r"(b1));
}

// ---------------- prep kernels ----------------
__global__ void prep_x(const float4* __restrict__ x){
    size_t i = (size_t)blockIdx.x * blockDim.x + threadIdx.x;
    float4 v = x[i];
    reinterpret_cast<__half2*>(g_Xh)[2*i]   = __floats2half2_rn(v.x, v.y);
    reinterpret_cast<__half2*>(g_Xh)[2*i+1] = __floats2half2_rn(v.z, v.w);
}

__global__ void prep_w(const float* __restrict__ W){
    __shared__ float t[32][33];
    const int bx = blockIdx.x, by = blockIdx.y;
    const int tx = threadIdx.x, ty = threadIdx.y;    // (32,8)
    #pragma unroll
    for (int i = 0; i < 32; i += 8)
        t[ty + i][tx] = W[(size_t)(by*32 + ty + i)*Dd + bx*32 + tx];
    __syncthreads();
    #pragma unroll
    for (int i = 0; i < 32; i += 8)
        g_Wh[(size_t)(bx*32 + ty + i)*DIN + by*32 + tx] = __float2half_rn(t[tx][ty + i]);
}

__global__ void prep_cent(const float* __restrict__ cent){
    const int row = blockIdx.x, tid = threadIdx.x;   // 256 threads
    const float4* src4 = reinterpret_cast<const float4*>(cent + (size_t)row * Dd);
    __half2* dst2 = reinterpret_cast<__half2*>(g_Ch + (size_t)row * Dd);
    float s = 0.f;
    if (tid < 192){
        float4 v = src4[tid];
        s = v.x*v.x + v.y*v.y + v.z*v.z + v.w*v.w;
        dst2[tid*2]   = __floats2half2_rn(v.x, v.y);
        dst2[tid*2+1] = __floats2half2_rn(v.z, v.w);
    }
    __shared__ float red[8];
    #pragma unroll
    for (int o = 16; o; o >>= 1) s += __shfl_down_sync(0xffffffffu, s, o);
    if ((tid & 31) == 0) red[tid >> 5] = s;
    __syncthreads();
    if (tid < 8){
        s = red[tid];
        #pragma unroll
        for (int o = 4; o; o >>= 1) s += __shfl_down_sync(0xffu, s, o);
        if (tid == 0) g_csq[row] = s;
    }
}

__global__ void combine_esq(){
    const int row = blockIdx.x * blockDim.x + threadIdx.x;
    const float* p = g_esqp + (size_t)row * 12;
    float s = 0.f;
    #pragma unroll
    for (int k = 0; k < 12; k++) s += p[k];
    g_esq[row] = s;
}

// tile constants: CTA 128x128, 4 warps (2x2 of 64x64), BK=64, 2 stages, 3 CTA/SM
static constexpr int A_ST1  = 128 * 128;             // 16 KB
static constexpr int STAGE1 = 2 * A_ST1;             // 32 KB
static constexpr int NSTG1  = 2;
static constexpr int SMEM1  = NSTG1 * STAGE1;        // 64 KB

// ------- fp16 GEMM (E producer): E = Xh @ Wh^T, f16 acc, stores fp16 E + esq partials -------
__global__ void __launch_bounds__(128, 3)
gemm_e(const __half* __restrict__ A, const __half* __restrict__ B)
{
    constexpr int NT = DIN / 64;                     // 16 k-chunks
    constexpr int LD = DIN * 2;

    extern __shared__ char smem[];
    const uint32_t sb = smem_u32(smem);
    const int tid = threadIdx.x, wid = tid >> 5, lane = tid & 31;
    const int warp_m = wid >> 1, warp_n = wid & 1;   // 2 x 2
    const int m0 = blockIdx.x * 128, n0 = blockIdx.y * 128;

    // hoisted per-thread global/smem addresses for the loader
    const int ldrow = tid >> 3, ldc = (tid & 7) * 16;
    const char* gAr = reinterpret_cast<const char*>(A) + (size_t)(m0 + ldrow) * LD + ldc;
    const char* gBr = reinterpret_cast<const char*>(B) + (size_t)(n0 + ldrow) * LD + ldc;
    uint32_t sOff[8];                                 // swizzled dst offsets (A rows 0..,16..)
    #pragma unroll
    for (int i = 0; i < 8; i++)
        sOff[i] = swz((uint32_t)((ldrow + i*16)*128 + ldc));

    auto load_stage = [&](int kc){
        const uint32_t base = sb + (kc & 1) * STAGE1;
        const size_t koff = (size_t)kc * 128;
        #pragma unroll
        for (int i = 0; i < 8; i++)
            cp16(base + sOff[i], gAr + (size_t)(i*16)*LD + koff);
        #pragma unroll
        for (int i = 0; i < 8; i++)
            cp16(base + A_ST1 + sOff[i], gBr + (size_t)(i*16)*LD + koff);
        cp_commit();
    };

    uint32_t hacc[4][8][2];
    #pragma unroll
    for (int i = 0; i < 4; i++)
        #pragma unroll
        for (int j = 0; j < 8; j++){ hacc[i][j][0] = 0u; hacc[i][j][1] = 0u; }

    load_stage(0); load_stage(1);
    const int lrow = lane & 15, lcol = (lane >> 4) * 16;

    // hoisted LDSM base offsets (ks=0); per-ks address = base ^ (ks*32)
    uint32_t aoff[4], boff[4];
    #pragma unroll
    for (int i = 0; i < 4; i++)
        aoff[i] = swz((uint32_t)((warp_m*64 + i*16 + lrow)*128 + lcol));
    #pragma unroll
    for (int j = 0; j < 4; j++)
        boff[j] = A_ST1 + swz((uint32_t)((warp_n*64 + j*16 + lrow)*128 + lcol));

    for (int kc = 0; kc < NT; kc++){
        cp_wait<1>();
        __syncthreads();
        const uint32_t sbs = sb + (kc & 1) * STAGE1;
        #pragma unroll
        for (int ks = 0; ks < 4; ks++){
            uint32_t a[4][4], b[4][4];
            const uint32_t kx = (uint32_t)(ks*32);
            #pragma unroll
            for (int i = 0; i < 4; i++)
                ldsm4(a[i], sbs + (aoff[i] ^ kx));
            #pragma unroll
            for (int j = 0; j < 4; j++)
                ldsm4(b[j], sbs + (boff[j] ^ kx));
            #pragma unroll
            for (int i = 0; i < 4; i++)
                #pragma unroll
                for (int j2 = 0; j2 < 8; j2++)
                    mma_f16(hacc[i][j2], a[i], b[j2>>1][j2&1], b[j2>>1][2 + (j2&1)]);
        }
        __syncthreads();
        if (kc + 2 < NT) load_stage(kc + 2);
        else             cp_commit();                 // uniform group counting
    }

    // epilogue: store fp16 E, esq partials from the SAME fp16 values
    const int quad = lane >> 2, tq = lane & 3;
    const int slot = blockIdx.y * 2 + warp_n;
    #pragma unroll
    for (int i = 0; i < 4; i++){
        const int mr0 = m0 + warp_m*64 + i*16 + quad;
        float s0 = 0.f, s1 = 0.f;
        #pragma unroll
        for (int j2 = 0; j2 < 8; j2++){
            const int n = n0 + warp_n*64 + j2*8 + tq*2;
            __half2 h0 = *reinterpret_cast<__half2*>(&hacc[i][j2][0]);
            __half2 h1 = *reinterpret_cast<__half2*>(&hacc[i][j2][1]);
            *reinterpret_cast<__half2*>(g_E + (size_t)mr0 * Dd + n)     = h0;
            *reinterpret_cast<__half2*>(g_E + (size_t)(mr0+8) * Dd + n) = h1;
            float2 f0 = __half22float2(h0), f1 = __half22float2(h1);
            s0 += f0.x*f0.x + f0.y*f0.y;
            s1 += f1.x*f1.x + f1.y*f1.y;
        }
        #pragma unroll
        for (int o = 1; o < 4; o <<= 1){
            s0 += __shfl_xor_sync(0xffffffffu, s0, o);
            s1 += __shfl_xor_sync(0xffffffffu, s1, o);
        }
        if (tq == 0){
            g_esqp[(size_t)mr0     * 12 + slot] = s0;
            g_esqp[(size_t)(mr0+8) * 12 + slot] = s1;
        }
    }
}

// ------- fp16 GEMM (output): out = 2*(E @ Ch^T) - esq - csq, f16 acc -------
__global__ void __launch_bounds__(128, 3)
gemm_h(const __half* __restrict__ A, const __half* __restrict__ B, float* __restrict__ out)
{
    constexpr int NT = Dd / 64;                      // 12 k-chunks
    constexpr int LD = Dd * 2;

    extern __shared__ char smem[];
    const uint32_t sb = smem_u32(smem);
    const int tid = threadIdx.x, wid = tid >> 5, lane = tid & 31;
    const int warp_m = wid >> 1, warp_n = wid & 1;   // 2 x 2
    const int m0 = blockIdx.x * 128, n0 = blockIdx.y * 128;

    const int ldrow = tid >> 3, ldc = (tid & 7) * 16;
    const char* gAr = reinterpret_cast<const char*>(A) + (size_t)(m0 + ldrow) * LD + ldc;
    const char* gBr = reinterpret_cast<const char*>(B) + (size_t)(n0 + ldrow) * LD + ldc;
    uint32_t sOff[8];
    #pragma unroll
    for (int i = 0; i < 8; i++)
        sOff[i] = swz((uint32_t)((ldrow + i*16)*128 + ldc));

    auto load_stage = [&](int kc){
        const uint32_t base = sb + (kc & 1) * STAGE1;
        const size_t koff = (size_t)kc * 128;
        #pragma unroll
        for (int i = 0; i < 8; i++)
            cp16(base + sOff[i], gAr + (size_t)(i*16)*LD + koff);
        #pragma unroll
        for (int i = 0; i < 8; i++)
            cp16(base + A_ST1 + sOff[i], gBr + (size_t)(i*16)*LD + koff);
        cp_commit();
    };

    uint32_t hacc[4][8][2];
    #pragma unroll
    for (int i = 0; i < 4; i++)
        #pragma unroll
        for (int j = 0; j < 8; j++){ hacc[i][j][0] = 0u; hacc[i][j][1] = 0u; }

    load_stage(0); load_stage(1);
    const int lrow = lane & 15, lcol = (lane >> 4) * 16;

    uint32_t aoff[4], boff[4];
    #pragma unroll
    for (int i = 0; i < 4; i++)
        aoff[i] = swz((uint32_t)((warp_m*64 + i*16 + lrow)*128 + lcol));
    #pragma unroll
    for (int j = 0; j < 4; j++)
        boff[j] = A_ST1 + swz((uint32_t)((warp_n*64 + j*16 + lrow)*128 + lcol));

    for (int kc = 0; kc < NT; kc++){
        cp_wait<1>();
        __syncthreads();
        const uint32_t sbs = sb + (kc & 1) * STAGE1;
        #pragma unroll
        for (int ks = 0; ks < 4; ks++){
            uint32_t a[4][4], b[4][4];
            const uint32_t kx = (uint32_t)(ks*32);
            #pragma unroll
            for (int i = 0; i < 4; i++)
                ldsm4(a[i], sbs + (aoff[i] ^ kx));
            #pragma unroll
            for (int j = 0; j < 4; j++)
                ldsm4(b[j], sbs + (boff[j] ^ kx));
            #pragma unroll
            for (int i = 0; i < 4; i++)
                #pragma unroll
                for (int j2 = 0; j2 < 8; j2++)
                    mma_f16(hacc[i][j2], a[i], b[j2>>1][j2&1], b[j2>>1][2 + (j2&1)]);
        }
        __syncthreads();
        if (kc + 2 < NT) load_stage(kc + 2);
        else             cp_commit();
    }

    const int quad = lane >> 2, tq = lane & 3;
    #pragma unroll
    for (int i = 0; i < 4; i++){
        const int mr0 = m0 + warp_m*64 + i*16 + quad;
        const float e0 = __ldg(&g_esq[mr0]), e1 = __ldg(&g_esq[mr0 + 8]);
        #pragma unroll
        for (int j2 = 0; j2 < 8; j2++){
            const int n = n0 + warp_n*64 + j2*8 + tq*2;
            const float cs0 = __ldg(&g_csq[n]), cs1 = __ldg(&g_csq[n+1]);
            float2 lo = __half22float2(*reinterpret_cast<__half2*>(&hacc[i][j2][0]));
            float2 hi = __half22float2(*reinterpret_cast<__half2*>(&hacc[i][j2][1]));
            float2 v0 = make_float2(2.f*lo.x - e0 - cs0, 2.f*lo.y - e0 - cs1);
            float2 v1 = make_float2(2.f*hi.x - e1 - cs0, 2.f*hi.y - e1 - cs1);
            *reinterpret_cast<float2*>(out + (size_t)mr0 * Cc + n)     = v0;
            *reinterpret_cast<float2*>(out + (size_t)(mr0+8) * Cc + n) = v1;
        }
    }
}

extern "C" void kernel_launch(void* const* d_in, const int* in_sizes, int n_in,
                              void* d_out, int out_size)
{
    const float* x = (const float*)d_in[0];
    const float* W = (const float*)d_in[1];
    const float* c = (const float*)d_in[2];
    float* out = (float*)d_out;

    cudaFuncSetAttribute(gemm_e, cudaFuncAttributeMaxDynamicSharedMemorySize, SMEM1);
    cudaFuncSetAttribute(gemm_h, cudaFuncAttributeMaxDynamicSharedMemorySize, SMEM1);

    prep_x<<<(Bn * DIN / 4) / 256, 256>>>(reinterpret_cast<const float4*>(x));
    prep_w<<<dim3(Dd / 32, DIN / 32), dim3(32, 8)>>>(W);
    prep_cent<<<Cc, 256>>>(c);

    __half *xh, *wh, *eh, *ch;
    cudaGetSymbolAddress((void**)&xh, g_Xh);
    cudaGetSymbolAddress((void**)&wh, g_Wh);
    cudaGetSymbolAddress((void**)&eh, g_E);
    cudaGetSymbolAddress((void**)&ch, g_Ch);

    gemm_e<<<dim3(Bn / 128, Dd / 128), 128, SMEM1>>>(xh, wh);
    combine_esq<<<Bn / 256, 256>>>();
    gemm_h<<<dim3(Bn / 128, Cc / 128), 128, SMEM1>>>(eh, ch, out);
}